// round 5
// baseline (speedup 1.0000x reference)
#include <cuda_runtime.h>
#include <cuda_bf16.h>
#include <cstdint>
#include <math.h>

// Problem constants
#define BB 2
#define SS 2048
#define HH 16
#define DD 128
#define NSTATE 2048
#define QKV_W (3*HH*DD)   // 6144

// ---------------- scratch (device globals; no runtime alloc) ----------------
__device__ float g_qkv[(size_t)BB * SS * QKV_W];    // [B,S,6144]
__device__ float g_attn[(size_t)BB * SS * HH * DD]; // [B,S,H,D]

// ---------------- helpers ----------------------------------------------------
__device__ __forceinline__ uint32_t tf32_rna(float x) {
    uint32_t r; asm("cvt.rna.tf32.f32 %0, %1;" : "=r"(r) : "f"(x)); return r;
}
__device__ __forceinline__ void mma_tf32_16x8x8(float* c, const uint32_t* a,
                                                const uint32_t* b) {
    asm volatile(
        "mma.sync.aligned.m16n8k8.row.col.f32.tf32.tf32.f32 "
        "{%0,%1,%2,%3}, {%4,%5,%6,%7}, {%8,%9}, {%0,%1,%2,%3};\n"
        : "+f"(c[0]), "+f"(c[1]), "+f"(c[2]), "+f"(c[3])
        : "r"(a[0]), "r"(a[1]), "r"(a[2]), "r"(a[3]), "r"(b[0]), "r"(b[1]));
}

// ============================================================================
// Fragment-packed smem layout.
// Tile [rows x K] stored so one uint4 = a thread's full mma fragment:
//   slot(g, rr, kk8, c): .x=(R,k0) .y=(R+8,k0) .z=(R,k0+4) .w=(R+8,k0+4)
//   where R = g*16+rr, k0 = kk8*8+c.  Slot index within (g,rr):
//   f = (kk8*4+c) ^ ((rr&1)<<2)  (parity swizzle -> conflict-free LDS.128).
// uint4 index: (g*8+rr)*(K/8*4) + f.  A-frag = {x,y,z,w};
// B-frags for n-tiles 2p,2p+1 = {x,z},{y,w}.
// ============================================================================
__device__ __forceinline__ void pack_write4(uint4* buf, int K, int row, int c4,
                                            float4 v) {
    int g = row >> 4, r16 = row & 15, rr = r16 & 7, hi = r16 >> 3;
    int kk8 = c4 >> 3, half = (c4 >> 2) & 1;
    int sw = (rr & 1) << 2;
    uint32_t* base = (uint32_t*)&buf[(size_t)(g * 8 + rr) * (K >> 1)];
    int w = hi + 2 * half;
    base[(((kk8 << 2) + 0) ^ sw) * 4 + w] = tf32_rna(v.x);
    base[(((kk8 << 2) + 1) ^ sw) * 4 + w] = tf32_rna(v.y);
    base[(((kk8 << 2) + 2) ^ sw) * 4 + w] = tf32_rna(v.z);
    base[(((kk8 << 2) + 3) ^ sw) * 4 + w] = tf32_rna(v.w);
}
__device__ __forceinline__ void pack_write1(uint4* buf, int K, int row, int k,
                                            uint32_t val) {
    int g = row >> 4, r16 = row & 15, rr = r16 & 7, hi = r16 >> 3;
    int kk8 = k >> 3, c = k & 3, half = (k >> 2) & 1;
    uint32_t* p = (uint32_t*)&buf[(size_t)(g * 8 + rr) * (K >> 1)
                                  + ((((kk8 << 2) + c) ^ ((rr & 1) << 2)))];
    p[hi + 2 * half] = val;
}

// ============================================================================
// tf32 mma.sync GEMM (NT): C[m,n] = sum_k A[m,k]*B[n,k] (+bias[n])
// Block 128x128x16, 8 warps (4x2), warp tile 32x64, double-buffered packed smem.
// ============================================================================
__global__ __launch_bounds__(256, 2)
void gemm_mma(const float* __restrict__ A, const float* __restrict__ B,
              const float* __restrict__ bias, float* __restrict__ C,
              int M, int N, int K) {
    __shared__ uint4 As[2][512];   // 128 rows x 16 k, packed
    __shared__ uint4 Bs[2][512];

    const int tid = threadIdx.x;
    const int w = tid >> 5, l = tid & 31;
    const int lr = l >> 2, lc = l & 3;
    const int wm = w >> 1, wn = w & 1;
    const int m0 = blockIdx.y * 128, n0 = blockIdx.x * 128;
    const int sw = (lr & 1) << 2;

    const int row = tid >> 2;          // 0..63 (also handles row+64)
    const int c4  = (tid & 3) * 4;     // 0,4,8,12

    float acc[2][8][4];
#pragma unroll
    for (int mt = 0; mt < 2; mt++)
#pragma unroll
        for (int nt = 0; nt < 8; nt++)
#pragma unroll
            for (int i = 0; i < 4; i++) acc[mt][nt][i] = 0.f;

    float4 pa0, pa1, pb0, pb1;
    const int NC = K / 16;

    pa0 = *(const float4*)&A[(size_t)(m0 + row) * K + c4];
    pa1 = *(const float4*)&A[(size_t)(m0 + row + 64) * K + c4];
    pb0 = *(const float4*)&B[(size_t)(n0 + row) * K + c4];
    pb1 = *(const float4*)&B[(size_t)(n0 + row + 64) * K + c4];
    pack_write4(As[0], 16, row,      c4, pa0);
    pack_write4(As[0], 16, row + 64, c4, pa1);
    pack_write4(Bs[0], 16, row,      c4, pb0);
    pack_write4(Bs[0], 16, row + 64, c4, pb1);
    __syncthreads();

    for (int c = 0; c < NC; c++) {
        const int buf = c & 1;
        if (c + 1 < NC) {
            const int k0 = (c + 1) * 16;
            pa0 = *(const float4*)&A[(size_t)(m0 + row) * K + k0 + c4];
            pa1 = *(const float4*)&A[(size_t)(m0 + row + 64) * K + k0 + c4];
            pb0 = *(const float4*)&B[(size_t)(n0 + row) * K + k0 + c4];
            pb1 = *(const float4*)&B[(size_t)(n0 + row + 64) * K + k0 + c4];
        }

        const uint4* __restrict__ a_s = As[buf];
        const uint4* __restrict__ b_s = Bs[buf];
#pragma unroll
        for (int kk = 0; kk < 2; kk++) {
            const int slot = ((kk << 2) + lc) ^ sw;
            uint32_t af[2][4];
#pragma unroll
            for (int mt = 0; mt < 2; mt++) {
                uint4 v = a_s[((wm * 2 + mt) * 8 + lr) * 8 + slot];
                af[mt][0] = v.x; af[mt][1] = v.y; af[mt][2] = v.z; af[mt][3] = v.w;
            }
            uint32_t bf[8][2];
#pragma unroll
            for (int p = 0; p < 4; p++) {
                uint4 v = b_s[((wn * 4 + p) * 8 + lr) * 8 + slot];
                bf[2 * p][0]     = v.x; bf[2 * p][1]     = v.z;
                bf[2 * p + 1][0] = v.y; bf[2 * p + 1][1] = v.w;
            }
#pragma unroll
            for (int mt = 0; mt < 2; mt++)
#pragma unroll
                for (int nt = 0; nt < 8; nt++)
                    mma_tf32_16x8x8(acc[mt][nt], af[mt], bf[nt]);
        }
        __syncthreads();

        if (c + 1 < NC) {
            const int nb = (c + 1) & 1;
            pack_write4(As[nb], 16, row,      c4, pa0);
            pack_write4(As[nb], 16, row + 64, c4, pa1);
            pack_write4(Bs[nb], 16, row,      c4, pb0);
            pack_write4(Bs[nb], 16, row + 64, c4, pb1);
            __syncthreads();
        }
    }

#pragma unroll
    for (int mt = 0; mt < 2; mt++) {
        int m = m0 + wm * 32 + mt * 16 + lr;
#pragma unroll
        for (int nt = 0; nt < 8; nt++) {
            int n = n0 + wn * 64 + nt * 8 + lc * 2;
            float bx = 0.f, by = 0.f;
            if (bias) { bx = bias[n]; by = bias[n + 1]; }
            float2 v0 = { acc[mt][nt][0] + bx, acc[mt][nt][1] + by };
            float2 v1 = { acc[mt][nt][2] + bx, acc[mt][nt][3] + by };
            *(float2*)&C[(size_t)m * N + n] = v0;
            *(float2*)&C[(size_t)(m + 8) * N + n] = v1;
        }
    }
}

// ---------------- RoPE (q in place, k -> out_k), v copy ---------------------
__global__ void rope_scatter(float* __restrict__ qkv,
                             const float* __restrict__ f_r,
                             const float* __restrict__ f_i,
                             float* __restrict__ out_k,
                             float* __restrict__ out_v) {
    int idx = blockIdx.x * blockDim.x + threadIdx.x;
    if (idx >= BB * SS * HH * 64) return;
    int d2 = idx & 63;
    int h  = (idx >> 6) & (HH - 1);
    int bs = idx >> 10;

    float fr = f_r[(size_t)bs * 64 + d2];
    float fi = f_i[(size_t)bs * 64 + d2];

    size_t base = (size_t)bs * QKV_W;
    size_t qi = base + (size_t)h * DD + d2;
    float xr = qkv[qi], xi = qkv[qi + 64];
    qkv[qi]      = xr * fr - xi * fi;
    qkv[qi + 64] = xr * fi + xi * fr;

    size_t ki = base + (size_t)HH * DD + (size_t)h * DD + d2;
    xr = qkv[ki]; xi = qkv[ki + 64];
    size_t ko = ((size_t)bs * HH + h) * DD + d2;
    out_k[ko]      = xr * fr - xi * fi;
    out_k[ko + 64] = xr * fi + xi * fr;

    size_t vi = base + (size_t)2 * HH * DD + (size_t)h * DD + d2;
    out_v[ko]      = qkv[vi];
    out_v[ko + 64] = qkv[vi + 64];
}

// ============================================================================
// Flash attention, tf32 mma.sync, fragment-packed smem.
// BM=128 (8 warps x 16 rows), BN=64, D=128.
// Qp[128xK128] Kp[64xK128] Vp[128(d) x K64(j)] Pp[128xK64].
// ============================================================================
#define FA_U4 (4096 + 2048 + 2048 + 2048)
#define FA_BYTES (FA_U4 * 16)

__global__ __launch_bounds__(256, 1)
void flash_attn(const float* __restrict__ qkv,
                const float* __restrict__ kbuf,
                const float* __restrict__ vbuf,
                const float* __restrict__ mask,
                float* __restrict__ attn_out) {
    extern __shared__ uint4 smq[];
    uint4* Qp = smq;                 // 4096 uint4
    uint4* Kp = Qp + 4096;           // 2048
    uint4* Vp = Kp + 2048;           // 2048
    uint4* Pp = Vp + 2048;           // 2048

    const int qb = blockIdx.x, h = blockIdx.y, b = blockIdx.z;
    const int tid = threadIdx.x, w = tid >> 5, l = tid & 31;
    const int lr = l >> 2, lc = l & 3;
    const int sw = (lr & 1) << 2;
    const float scale = 0.08838834764831845f;   // 1/sqrt(128)

    // ---- load Q tile (prescaled, tf32, packed) ----
    for (int t = tid; t < 128 * 32; t += 256) {
        int r = t >> 5, c4 = (t & 31) * 4;
        float4 v = *(const float4*)&qkv[((size_t)b * SS + qb * 128 + r) * QKV_W
                                        + h * DD + c4];
        v.x *= scale; v.y *= scale; v.z *= scale; v.w *= scale;
        pack_write4(Qp, 128, r, c4, v);
    }

    float O[16][4];
#pragma unroll
    for (int nt = 0; nt < 16; nt++)
#pragma unroll
        for (int i = 0; i < 4; i++) O[nt][i] = 0.f;
    float m_lo = -INFINITY, m_hi = -INFINITY, l_lo = 0.f, l_hi = 0.f;

    const int nKV = 2 * qb + 2;                  // causal block count

    for (int kb = 0; kb < nKV; kb++) {
        __syncthreads();   // prior iter's Kp/Vp reads complete; Qp ready (iter 0)
        // ---- load K (packed rows=n, K=128) and V (packed rows=d, K=64) ----
        for (int t = tid; t < 64 * 32; t += 256) {
            int r = t >> 5, c4 = (t & 31) * 4;
            size_t src = ((size_t)b * SS + kb * 64 + r) * (HH * DD)
                       + (size_t)h * DD + c4;
            float4 kv = *(const float4*)&kbuf[src];
            pack_write4(Kp, 128, r, c4, kv);
            float4 vv = *(const float4*)&vbuf[src];
            pack_write1(Vp, 64, c4 + 0, r, tf32_rna(vv.x));
            pack_write1(Vp, 64, c4 + 1, r, tf32_rna(vv.y));
            pack_write1(Vp, 64, c4 + 2, r, tf32_rna(vv.z));
            pack_write1(Vp, 64, c4 + 3, r, tf32_rna(vv.w));
        }
        __syncthreads();

        // ---- S = Q K^T : m16 x n64 x k128 per warp ----
        float S[8][4];
#pragma unroll
        for (int nt = 0; nt < 8; nt++)
#pragma unroll
            for (int i = 0; i < 4; i++) S[nt][i] = 0.f;
#pragma unroll
        for (int ks = 0; ks < 16; ks++) {
            const int slot = ((ks << 2) + lc) ^ sw;
            uint4 qv = Qp[(w * 8 + lr) * 64 + slot];
            uint32_t af[4] = { qv.x, qv.y, qv.z, qv.w };
#pragma unroll
            for (int p = 0; p < 4; p++) {
                uint4 kv = Kp[(p * 8 + lr) * 64 + slot];
                uint32_t b0[2] = { kv.x, kv.z };
                uint32_t b1[2] = { kv.y, kv.w };
                mma_tf32_16x8x8(S[2 * p], af, b0);
                mma_tf32_16x8x8(S[2 * p + 1], af, b1);
            }
        }

        // ---- diagonal blocks: add gmem mask ----
        if (kb >= 2 * qb) {
            const int m_glo = qb * 128 + w * 16 + lr;
            const float* mr0 = &mask[((size_t)b * SS + m_glo) * SS + kb * 64];
            const float* mr1 = mr0 + 8 * SS;
#pragma unroll
            for (int nt = 0; nt < 8; nt++) {
                float2 q0 = *(const float2*)&mr0[nt * 8 + lc * 2];
                float2 q1 = *(const float2*)&mr1[nt * 8 + lc * 2];
                S[nt][0] += q0.x; S[nt][1] += q0.y;
                S[nt][2] += q1.x; S[nt][3] += q1.y;
            }
        }

        // ---- online softmax (rows lr and lr+8) ----
        float bm_lo = -INFINITY, bm_hi = -INFINITY;
#pragma unroll
        for (int nt = 0; nt < 8; nt++) {
            bm_lo = fmaxf(bm_lo, fmaxf(S[nt][0], S[nt][1]));
            bm_hi = fmaxf(bm_hi, fmaxf(S[nt][2], S[nt][3]));
        }
        bm_lo = fmaxf(bm_lo, __shfl_xor_sync(0xffffffff, bm_lo, 1));
        bm_lo = fmaxf(bm_lo, __shfl_xor_sync(0xffffffff, bm_lo, 2));
        bm_hi = fmaxf(bm_hi, __shfl_xor_sync(0xffffffff, bm_hi, 1));
        bm_hi = fmaxf(bm_hi, __shfl_xor_sync(0xffffffff, bm_hi, 2));
        float mn_lo = fmaxf(m_lo, bm_lo);
        float mn_hi = fmaxf(m_hi, bm_hi);

        float rs_lo = 0.f, rs_hi = 0.f;
#pragma unroll
        for (int nt = 0; nt < 8; nt++) {
            S[nt][0] = __expf(S[nt][0] - mn_lo);
            S[nt][1] = __expf(S[nt][1] - mn_lo);
            S[nt][2] = __expf(S[nt][2] - mn_hi);
            S[nt][3] = __expf(S[nt][3] - mn_hi);
            rs_lo += S[nt][0] + S[nt][1];
            rs_hi += S[nt][2] + S[nt][3];
        }
        rs_lo += __shfl_xor_sync(0xffffffff, rs_lo, 1);
        rs_lo += __shfl_xor_sync(0xffffffff, rs_lo, 2);
        rs_hi += __shfl_xor_sync(0xffffffff, rs_hi, 1);
        rs_hi += __shfl_xor_sync(0xffffffff, rs_hi, 2);

        float al_lo = __expf(m_lo - mn_lo);
        float al_hi = __expf(m_hi - mn_hi);
        l_lo = l_lo * al_lo + rs_lo;
        l_hi = l_hi * al_hi + rs_hi;
        m_lo = mn_lo; m_hi = mn_hi;
#pragma unroll
        for (int nt = 0; nt < 16; nt++) {
            O[nt][0] *= al_lo; O[nt][1] *= al_lo;
            O[nt][2] *= al_hi; O[nt][3] *= al_hi;
        }

        // ---- stage P (warp-local, packed rows g=w) ----
#pragma unroll
        for (int nt = 0; nt < 8; nt++) {
            int k0 = nt * 8 + lc * 2;
            pack_write1(Pp, 64, w * 16 + lr,     k0,     tf32_rna(S[nt][0]));
            pack_write1(Pp, 64, w * 16 + lr,     k0 + 1, tf32_rna(S[nt][1]));
            pack_write1(Pp, 64, w * 16 + lr + 8, k0,     tf32_rna(S[nt][2]));
            pack_write1(Pp, 64, w * 16 + lr + 8, k0 + 1, tf32_rna(S[nt][3]));
        }
        __syncwarp();

        // ---- O += P V : m16 x n128 x k64 per warp ----
#pragma unroll
        for (int ks = 0; ks < 8; ks++) {
            const int slot = ((ks << 2) + lc) ^ sw;
            uint4 pv = Pp[(w * 8 + lr) * 32 + slot];
            uint32_t af[4] = { pv.x, pv.y, pv.z, pv.w };
#pragma unroll
            for (int p = 0; p < 8; p++) {
                uint4 vv = Vp[(p * 8 + lr) * 32 + slot];
                uint32_t b0[2] = { vv.x, vv.z };
                uint32_t b1[2] = { vv.y, vv.w };
                mma_tf32_16x8x8(O[2 * p], af, b0);
                mma_tf32_16x8x8(O[2 * p + 1], af, b1);
            }
        }
        __syncwarp();   // Pp reads done before next iter overwrites
    }

    // ---- epilogue: normalize, write [B,S,H,D] ----
    const float inv_lo = 1.0f / l_lo, inv_hi = 1.0f / l_hi;
    const int m0 = qb * 128 + w * 16 + lr;
#pragma unroll
    for (int nt = 0; nt < 16; nt++) {
        int d = nt * 8 + lc * 2;
        float2 v0 = { O[nt][0] * inv_lo, O[nt][1] * inv_lo };
        float2 v1 = { O[nt][2] * inv_hi, O[nt][3] * inv_hi };
        *(float2*)&attn_out[(((size_t)b * SS + m0) * HH + h) * DD + d] = v0;
        *(float2*)&attn_out[(((size_t)b * SS + m0 + 8) * HH + h) * DD + d] = v1;
    }
}

// ---------------- launch ----------------------------------------------------
extern "C" void kernel_launch(void* const* d_in, const int* in_sizes, int n_in,
                              void* d_out, int out_size) {
    const float* x      = (const float*)d_in[0];
    const float* f_r    = (const float*)d_in[1];
    const float* f_i    = (const float*)d_in[2];
    const float* mask   = (const float*)d_in[3];
    const float* W_qkv  = (const float*)d_in[4];
    const float* b_qkv  = (const float*)d_in[5];
    const float* W_o    = (const float*)d_in[6];

    float* out   = (float*)d_out;
    float* out_k = out   + (size_t)BB * SS * NSTATE;
    float* out_v = out_k + (size_t)BB * SS * HH * DD;

    float* qkv  = nullptr; cudaGetSymbolAddress((void**)&qkv,  g_qkv);
    float* attn = nullptr; cudaGetSymbolAddress((void**)&attn, g_attn);

    const int M = BB * SS;   // 4096

    cudaFuncSetAttribute(flash_attn, cudaFuncAttributeMaxDynamicSharedMemorySize,
                         FA_BYTES);

    // 1) QKV projection (tf32 mma.sync)
    gemm_mma<<<dim3(QKV_W / 128, M / 128), 256>>>(x, W_qkv, b_qkv, qkv,
                                                  M, QKV_W, NSTATE);
    // 2) RoPE q,k; scatter k,v to output
    rope_scatter<<<(BB * SS * HH * 64) / 256, 256>>>(qkv, f_r, f_i, out_k, out_v);
    // 3) attention (tf32 mma, packed smem, causal block skip)
    flash_attn<<<dim3(SS / 128, HH, BB), 256, FA_BYTES>>>(qkv, out_k, out_v,
                                                          mask, attn);
    // 4) output projection (tf32 mma.sync)
    gemm_mma<<<dim3(NSTATE / 128, M / 128), 256>>>(attn, W_o, nullptr, out,
                                                   M, NSTATE, NSTATE);
}

// round 6
// speedup vs baseline: 1.5904x; 1.5904x over previous
#include <cuda_runtime.h>
#include <cuda_bf16.h>
#include <cstdint>
#include <math.h>

// Problem constants
#define BB 2
#define SS 2048
#define HH 16
#define DD 128
#define NSTATE 2048
#define QKV_W (3*HH*DD)   // 6144

// ---------------- scratch (device globals; no runtime alloc) ----------------
__device__ float g_qkv[(size_t)BB * SS * QKV_W];    // [B,S,6144]
__device__ float g_attn[(size_t)BB * SS * HH * DD]; // [B,S,H,D]

// ---------------- helpers ----------------------------------------------------
__device__ __forceinline__ uint32_t tf32_rna(float x) {
    uint32_t r; asm("cvt.rna.tf32.f32 %0, %1;" : "=r"(r) : "f"(x)); return r;
}
__device__ __forceinline__ uint32_t smem_u32(const void* p) {
    uint32_t a;
    asm("{ .reg .u64 t; cvta.to.shared.u64 t, %1; cvt.u32.u64 %0, t; }"
        : "=r"(a) : "l"(p));
    return a;
}
__device__ __forceinline__ void mma_tf32_16x8x8(float* c, const uint32_t* a,
                                                const uint32_t* b) {
    asm volatile(
        "mma.sync.aligned.m16n8k8.row.col.f32.tf32.tf32.f32 "
        "{%0,%1,%2,%3}, {%4,%5,%6,%7}, {%8,%9}, {%0,%1,%2,%3};\n"
        : "+f"(c[0]), "+f"(c[1]), "+f"(c[2]), "+f"(c[3])
        : "r"(a[0]), "r"(a[1]), "r"(a[2]), "r"(a[3]), "r"(b[0]), "r"(b[1]));
}
// ldmatrix x4 on 32-bit data: each 8x8 b16 matrix = 8 rows x 4 tf32;
// lane l receives element (row l/4, col l%4) of matrix (reg index).
__device__ __forceinline__ void ldsm_x4(uint32_t* r, uint32_t addr) {
    asm volatile("ldmatrix.sync.aligned.m8n8.x4.shared.b16 {%0,%1,%2,%3}, [%4];"
                 : "=r"(r[0]), "=r"(r[1]), "=r"(r[2]), "=r"(r[3]) : "r"(addr));
}

// ============================================================================
// tf32 mma.sync GEMM (NT): C[m,n] = sum_k A[m,k]*B[n,k] (+bias[n])
// Block tile 128x128x16, 8 warps (4x2), warp tile 32x64, double-buffered smem,
// TPAD=20 padded rows, fragments loaded via ldmatrix.x4.
// ============================================================================
#define TPAD 20

__global__ __launch_bounds__(256, 2)
void gemm_mma(const float* __restrict__ A, const float* __restrict__ B,
              const float* __restrict__ bias, float* __restrict__ C,
              int M, int N, int K) {
    __shared__ uint32_t As[2][128 * TPAD];
    __shared__ uint32_t Bs[2][128 * TPAD];

    const int tid = threadIdx.x;
    const int w = tid >> 5, l = tid & 31;
    const int lr = l >> 2, lc = l & 3;
    const int wm = w >> 1, wn = w & 1;
    const int m0 = blockIdx.y * 128, n0 = blockIdx.x * 128;

    const int row = tid >> 2;
    const int c4  = (tid & 3) * 4;

    // ldmatrix per-lane source mapping
    const int mat = l >> 3;
    const uint32_t sA = smem_u32(&As[0][0]);
    const uint32_t sB = smem_u32(&Bs[0][0]);
    const uint32_t BUFB = 128 * TPAD * 4;
    // A: mat0 rows 0-7 k0, mat1 rows 8-15 k0, mat2 rows 0-7 k0+4, mat3 rows 8-15 k0+4
    const uint32_t aFrag = sA + (uint32_t)(((wm * 32 + (mat & 1) * 8 + (l & 7)) * TPAD)
                                           + (mat >> 1) * 4) * 4;
    // B: mat0 rows 0-7 k0 (b0,t2p), mat1 rows 0-7 k0+4 (b1,t2p),
    //    mat2 rows 8-15 k0 (b0,t2p+1), mat3 rows 8-15 k0+4 (b1,t2p+1)
    const uint32_t bFrag = sB + (uint32_t)(((wn * 64 + (mat >> 1) * 8 + (l & 7)) * TPAD)
                                           + (mat & 1) * 4) * 4;

    float acc[2][8][4];
#pragma unroll
    for (int mt = 0; mt < 2; mt++)
#pragma unroll
        for (int nt = 0; nt < 8; nt++)
#pragma unroll
            for (int i = 0; i < 4; i++) acc[mt][nt][i] = 0.f;

    float4 pa0, pa1, pb0, pb1;
    const int NC = K / 16;

    pa0 = *(const float4*)&A[(size_t)(m0 + row) * K + c4];
    pa1 = *(const float4*)&A[(size_t)(m0 + row + 64) * K + c4];
    pb0 = *(const float4*)&B[(size_t)(n0 + row) * K + c4];
    pb1 = *(const float4*)&B[(size_t)(n0 + row + 64) * K + c4];
    {
        uint32_t* a = As[0]; uint32_t* b = Bs[0];
        a[row * TPAD + c4 + 0] = tf32_rna(pa0.x); a[row * TPAD + c4 + 1] = tf32_rna(pa0.y);
        a[row * TPAD + c4 + 2] = tf32_rna(pa0.z); a[row * TPAD + c4 + 3] = tf32_rna(pa0.w);
        a[(row + 64) * TPAD + c4 + 0] = tf32_rna(pa1.x); a[(row + 64) * TPAD + c4 + 1] = tf32_rna(pa1.y);
        a[(row + 64) * TPAD + c4 + 2] = tf32_rna(pa1.z); a[(row + 64) * TPAD + c4 + 3] = tf32_rna(pa1.w);
        b[row * TPAD + c4 + 0] = tf32_rna(pb0.x); b[row * TPAD + c4 + 1] = tf32_rna(pb0.y);
        b[row * TPAD + c4 + 2] = tf32_rna(pb0.z); b[row * TPAD + c4 + 3] = tf32_rna(pb0.w);
        b[(row + 64) * TPAD + c4 + 0] = tf32_rna(pb1.x); b[(row + 64) * TPAD + c4 + 1] = tf32_rna(pb1.y);
        b[(row + 64) * TPAD + c4 + 2] = tf32_rna(pb1.z); b[(row + 64) * TPAD + c4 + 3] = tf32_rna(pb1.w);
    }
    __syncthreads();

    for (int c = 0; c < NC; c++) {
        const uint32_t bo = (c & 1) ? BUFB : 0u;
        if (c + 1 < NC) {
            const int k0 = (c + 1) * 16;
            pa0 = *(const float4*)&A[(size_t)(m0 + row) * K + k0 + c4];
            pa1 = *(const float4*)&A[(size_t)(m0 + row + 64) * K + k0 + c4];
            pb0 = *(const float4*)&B[(size_t)(n0 + row) * K + k0 + c4];
            pb1 = *(const float4*)&B[(size_t)(n0 + row + 64) * K + k0 + c4];
        }

#pragma unroll
        for (int kk = 0; kk < 2; kk++) {
            uint32_t af[2][4];
            ldsm_x4(af[0], aFrag + bo + kk * 32);
            ldsm_x4(af[1], aFrag + bo + kk * 32 + 16 * TPAD * 4);
            uint32_t bf[8][2];
#pragma unroll
            for (int p = 0; p < 4; p++) {
                uint32_t r[4];
                ldsm_x4(r, bFrag + bo + kk * 32 + p * (16 * TPAD * 4));
                bf[2 * p][0] = r[0];     bf[2 * p][1] = r[1];
                bf[2 * p + 1][0] = r[2]; bf[2 * p + 1][1] = r[3];
            }
#pragma unroll
            for (int mt = 0; mt < 2; mt++)
#pragma unroll
                for (int nt = 0; nt < 8; nt++)
                    mma_tf32_16x8x8(acc[mt][nt], af[mt], bf[nt]);
        }
        __syncthreads();

        if (c + 1 < NC) {
            const int nb = (c + 1) & 1;
            uint32_t* a = As[nb]; uint32_t* b = Bs[nb];
            a[row * TPAD + c4 + 0] = tf32_rna(pa0.x); a[row * TPAD + c4 + 1] = tf32_rna(pa0.y);
            a[row * TPAD + c4 + 2] = tf32_rna(pa0.z); a[row * TPAD + c4 + 3] = tf32_rna(pa0.w);
            a[(row + 64) * TPAD + c4 + 0] = tf32_rna(pa1.x); a[(row + 64) * TPAD + c4 + 1] = tf32_rna(pa1.y);
            a[(row + 64) * TPAD + c4 + 2] = tf32_rna(pa1.z); a[(row + 64) * TPAD + c4 + 3] = tf32_rna(pa1.w);
            b[row * TPAD + c4 + 0] = tf32_rna(pb0.x); b[row * TPAD + c4 + 1] = tf32_rna(pb0.y);
            b[row * TPAD + c4 + 2] = tf32_rna(pb0.z); b[row * TPAD + c4 + 3] = tf32_rna(pb0.w);
            b[(row + 64) * TPAD + c4 + 0] = tf32_rna(pb1.x); b[(row + 64) * TPAD + c4 + 1] = tf32_rna(pb1.y);
            b[(row + 64) * TPAD + c4 + 2] = tf32_rna(pb1.z); b[(row + 64) * TPAD + c4 + 3] = tf32_rna(pb1.w);
            __syncthreads();
        }
    }

#pragma unroll
    for (int mt = 0; mt < 2; mt++) {
        int m = m0 + wm * 32 + mt * 16 + lr;
#pragma unroll
        for (int nt = 0; nt < 8; nt++) {
            int n = n0 + wn * 64 + nt * 8 + lc * 2;
            float bx = 0.f, by = 0.f;
            if (bias) { bx = bias[n]; by = bias[n + 1]; }
            float2 v0 = { acc[mt][nt][0] + bx, acc[mt][nt][1] + by };
            float2 v1 = { acc[mt][nt][2] + bx, acc[mt][nt][3] + by };
            *(float2*)&C[(size_t)m * N + n] = v0;
            *(float2*)&C[(size_t)(m + 8) * N + n] = v1;
        }
    }
}

// ---------------- RoPE (q in place, k -> out_k), v copy ---------------------
__global__ void rope_scatter(float* __restrict__ qkv,
                             const float* __restrict__ f_r,
                             const float* __restrict__ f_i,
                             float* __restrict__ out_k,
                             float* __restrict__ out_v) {
    int idx = blockIdx.x * blockDim.x + threadIdx.x;
    if (idx >= BB * SS * HH * 64) return;
    int d2 = idx & 63;
    int h  = (idx >> 6) & (HH - 1);
    int bs = idx >> 10;

    float fr = f_r[(size_t)bs * 64 + d2];
    float fi = f_i[(size_t)bs * 64 + d2];

    size_t base = (size_t)bs * QKV_W;
    size_t qi = base + (size_t)h * DD + d2;
    float xr = qkv[qi], xi = qkv[qi + 64];
    qkv[qi]      = xr * fr - xi * fi;
    qkv[qi + 64] = xr * fi + xi * fr;

    size_t ki = base + (size_t)HH * DD + (size_t)h * DD + d2;
    xr = qkv[ki]; xi = qkv[ki + 64];
    size_t ko = ((size_t)bs * HH + h) * DD + d2;
    out_k[ko]      = xr * fr - xi * fi;
    out_k[ko + 64] = xr * fi + xi * fr;

    size_t vi = base + (size_t)2 * HH * DD + (size_t)h * DD + d2;
    out_v[ko]      = qkv[vi];
    out_v[ko + 64] = qkv[vi + 64];
}

// ============================================================================
// Flash attention on tf32 mma.sync + ldmatrix. BM=128 (8 warps x 16), BN=64.
// Q,K tf32 smem; V transposed (Vt[d][j]); P per-warp smem. Causal block skip.
// ============================================================================
#define QP 132
#define KP 132
#define VP 68
#define PP 68
#define FA_WORDS (128*QP + 64*KP + 128*VP + 128*PP)
#define FA_BYTES (FA_WORDS * 4)

__global__ __launch_bounds__(256, 1)
void flash_attn(const float* __restrict__ qkv,
                const float* __restrict__ kbuf,
                const float* __restrict__ vbuf,
                const float* __restrict__ mask,
                float* __restrict__ attn_out) {
    extern __shared__ uint32_t smw[];
    uint32_t* Qs = smw;                 // [128][QP] tf32
    uint32_t* Ks = Qs + 128 * QP;       // [64][KP]
    uint32_t* Vt = Ks + 64 * KP;        // [128][VP] (V transposed: [d][j])
    uint32_t* Ps = Vt + 128 * VP;       // [128][PP]

    const int qb = blockIdx.x, h = blockIdx.y, b = blockIdx.z;
    const int tid = threadIdx.x, w = tid >> 5, l = tid & 31;
    const int lr = l >> 2, lc = l & 3;
    const float scale = 0.08838834764831845f;   // 1/sqrt(128)

    // ldmatrix per-lane fragment addresses
    const int mat = l >> 3;
    const uint32_t sQ = smem_u32(Qs), sK = smem_u32(Ks);
    const uint32_t sV = smem_u32(Vt), sP = smem_u32(Ps);
    const uint32_t qFrag = sQ + (uint32_t)(((w * 16 + (mat & 1) * 8 + (l & 7)) * QP)
                                           + (mat >> 1) * 4) * 4;
    const uint32_t kFrag = sK + (uint32_t)((((mat >> 1) * 8 + (l & 7)) * KP)
                                           + (mat & 1) * 4) * 4;
    const uint32_t vFrag = sV + (uint32_t)((((mat >> 1) * 8 + (l & 7)) * VP)
                                           + (mat & 1) * 4) * 4;
    const uint32_t pFrag = sP + (uint32_t)(((w * 16 + (mat & 1) * 8 + (l & 7)) * PP)
                                           + (mat >> 1) * 4) * 4;

    // ---- load Q tile (prescaled, tf32) ----
    for (int t = tid; t < 128 * 32; t += 256) {
        int r = t >> 5, c4 = (t & 31) * 4;
        float4 v = *(const float4*)&qkv[((size_t)b * SS + qb * 128 + r) * QKV_W
                                        + h * DD + c4];
        uint32_t* dst = &Qs[r * QP + c4];
        dst[0] = tf32_rna(v.x * scale); dst[1] = tf32_rna(v.y * scale);
        dst[2] = tf32_rna(v.z * scale); dst[3] = tf32_rna(v.w * scale);
    }

    float O[16][4];
#pragma unroll
    for (int nt = 0; nt < 16; nt++)
#pragma unroll
        for (int i = 0; i < 4; i++) O[nt][i] = 0.f;
    float m_lo = -INFINITY, m_hi = -INFINITY, l_lo = 0.f, l_hi = 0.f;

    const int aP = (w * 16 + lr) * PP;
    const int nKV = 2 * qb + 2;                  // causal block count

    for (int kb = 0; kb < nKV; kb++) {
        __syncthreads();   // prior iter's Ks/Vt reads complete
        // ---- load K (row-major) and V (transposed), tf32 ----
        for (int t = tid; t < 64 * 32; t += 256) {
            int r = t >> 5, c4 = (t & 31) * 4;
            size_t src = ((size_t)b * SS + kb * 64 + r) * (HH * DD)
                       + (size_t)h * DD + c4;
            float4 kv = *(const float4*)&kbuf[src];
            uint32_t* kd = &Ks[r * KP + c4];
            kd[0] = tf32_rna(kv.x); kd[1] = tf32_rna(kv.y);
            kd[2] = tf32_rna(kv.z); kd[3] = tf32_rna(kv.w);
            float4 vv = *(const float4*)&vbuf[src];
            Vt[(c4 + 0) * VP + r] = tf32_rna(vv.x);
            Vt[(c4 + 1) * VP + r] = tf32_rna(vv.y);
            Vt[(c4 + 2) * VP + r] = tf32_rna(vv.z);
            Vt[(c4 + 3) * VP + r] = tf32_rna(vv.w);
        }
        __syncthreads();

        // ---- S = Q K^T : m16 x n64 x k128 per warp ----
        float S[8][4];
#pragma unroll
        for (int nt = 0; nt < 8; nt++)
#pragma unroll
            for (int i = 0; i < 4; i++) S[nt][i] = 0.f;
#pragma unroll
        for (int ks = 0; ks < 16; ks++) {
            uint32_t af[4];
            ldsm_x4(af, qFrag + ks * 32);
#pragma unroll
            for (int p = 0; p < 4; p++) {
                uint32_t r[4];
                ldsm_x4(r, kFrag + ks * 32 + p * (16 * KP * 4));
                mma_tf32_16x8x8(S[2 * p], af, r);
                mma_tf32_16x8x8(S[2 * p + 1], af, r + 2);
            }
        }

        // ---- diagonal blocks: add gmem mask ----
        if (kb >= 2 * qb) {
            const int m_glo = qb * 128 + w * 16 + lr;
            const float* mr0 = &mask[((size_t)b * SS + m_glo) * SS + kb * 64];
            const float* mr1 = mr0 + 8 * SS;
#pragma unroll
            for (int nt = 0; nt < 8; nt++) {
                float2 q0 = *(const float2*)&mr0[nt * 8 + lc * 2];
                float2 q1 = *(const float2*)&mr1[nt * 8 + lc * 2];
                S[nt][0] += q0.x; S[nt][1] += q0.y;
                S[nt][2] += q1.x; S[nt][3] += q1.y;
            }
        }

        // ---- online softmax (rows lr and lr+8) ----
        float bm_lo = -INFINITY, bm_hi = -INFINITY;
#pragma unroll
        for (int nt = 0; nt < 8; nt++) {
            bm_lo = fmaxf(bm_lo, fmaxf(S[nt][0], S[nt][1]));
            bm_hi = fmaxf(bm_hi, fmaxf(S[nt][2], S[nt][3]));
        }
        bm_lo = fmaxf(bm_lo, __shfl_xor_sync(0xffffffff, bm_lo, 1));
        bm_lo = fmaxf(bm_lo, __shfl_xor_sync(0xffffffff, bm_lo, 2));
        bm_hi = fmaxf(bm_hi, __shfl_xor_sync(0xffffffff, bm_hi, 1));
        bm_hi = fmaxf(bm_hi, __shfl_xor_sync(0xffffffff, bm_hi, 2));
        float mn_lo = fmaxf(m_lo, bm_lo);
        float mn_hi = fmaxf(m_hi, bm_hi);

        float rs_lo = 0.f, rs_hi = 0.f;
#pragma unroll
        for (int nt = 0; nt < 8; nt++) {
            S[nt][0] = __expf(S[nt][0] - mn_lo);
            S[nt][1] = __expf(S[nt][1] - mn_lo);
            S[nt][2] = __expf(S[nt][2] - mn_hi);
            S[nt][3] = __expf(S[nt][3] - mn_hi);
            rs_lo += S[nt][0] + S[nt][1];
            rs_hi += S[nt][2] + S[nt][3];
        }
        rs_lo += __shfl_xor_sync(0xffffffff, rs_lo, 1);
        rs_lo += __shfl_xor_sync(0xffffffff, rs_lo, 2);
        rs_hi += __shfl_xor_sync(0xffffffff, rs_hi, 1);
        rs_hi += __shfl_xor_sync(0xffffffff, rs_hi, 2);

        float al_lo = __expf(m_lo - mn_lo);
        float al_hi = __expf(m_hi - mn_hi);
        l_lo = l_lo * al_lo + rs_lo;
        l_hi = l_hi * al_hi + rs_hi;
        m_lo = mn_lo; m_hi = mn_hi;
#pragma unroll
        for (int nt = 0; nt < 16; nt++) {
            O[nt][0] *= al_lo; O[nt][1] *= al_lo;
            O[nt][2] *= al_hi; O[nt][3] *= al_hi;
        }

        // ---- stage P (warp-local) as tf32 ----
#pragma unroll
        for (int nt = 0; nt < 8; nt++) {
            int cw = nt * 8 + lc * 2;
            uint2 p0 = { tf32_rna(S[nt][0]), tf32_rna(S[nt][1]) };
            uint2 p1 = { tf32_rna(S[nt][2]), tf32_rna(S[nt][3]) };
            *(uint2*)&Ps[aP + cw] = p0;
            *(uint2*)&Ps[aP + 8 * PP + cw] = p1;
        }
        __syncwarp();

        // ---- O += P V : m16 x n128 x k64 per warp ----
#pragma unroll
        for (int ks = 0; ks < 8; ks++) {
            uint32_t af[4];
            ldsm_x4(af, pFrag + ks * 32);
#pragma unroll
            for (int p = 0; p < 8; p++) {
                uint32_t r[4];
                ldsm_x4(r, vFrag + ks * 32 + p * (16 * VP * 4));
                mma_tf32_16x8x8(O[2 * p], af, r);
                mma_tf32_16x8x8(O[2 * p + 1], af, r + 2);
            }
        }
        __syncwarp();   // Ps reads done before next iter overwrites
    }

    // ---- epilogue: normalize, write [B,S,H,D] ----
    const float inv_lo = 1.0f / l_lo, inv_hi = 1.0f / l_hi;
    const int m0 = qb * 128 + w * 16 + lr;
#pragma unroll
    for (int nt = 0; nt < 16; nt++) {
        int d = nt * 8 + lc * 2;
        float2 v0 = { O[nt][0] * inv_lo, O[nt][1] * inv_lo };
        float2 v1 = { O[nt][2] * inv_hi, O[nt][3] * inv_hi };
        *(float2*)&attn_out[(((size_t)b * SS + m0) * HH + h) * DD + d] = v0;
        *(float2*)&attn_out[(((size_t)b * SS + m0 + 8) * HH + h) * DD + d] = v1;
    }
}

// ---------------- launch ----------------------------------------------------
extern "C" void kernel_launch(void* const* d_in, const int* in_sizes, int n_in,
                              void* d_out, int out_size) {
    const float* x      = (const float*)d_in[0];
    const float* f_r    = (const float*)d_in[1];
    const float* f_i    = (const float*)d_in[2];
    const float* mask   = (const float*)d_in[3];
    const float* W_qkv  = (const float*)d_in[4];
    const float* b_qkv  = (const float*)d_in[5];
    const float* W_o    = (const float*)d_in[6];

    float* out   = (float*)d_out;
    float* out_k = out   + (size_t)BB * SS * NSTATE;
    float* out_v = out_k + (size_t)BB * SS * HH * DD;

    float* qkv  = nullptr; cudaGetSymbolAddress((void**)&qkv,  g_qkv);
    float* attn = nullptr; cudaGetSymbolAddress((void**)&attn, g_attn);

    const int M = BB * SS;   // 4096

    cudaFuncSetAttribute(flash_attn, cudaFuncAttributeMaxDynamicSharedMemorySize,
                         FA_BYTES);

    // 1) QKV projection (tf32 mma.sync + ldmatrix)
    gemm_mma<<<dim3(QKV_W / 128, M / 128), 256>>>(x, W_qkv, b_qkv, qkv,
                                                  M, QKV_W, NSTATE);
    // 2) RoPE q,k; scatter k,v to output
    rope_scatter<<<(BB * SS * HH * 64) / 256, 256>>>(qkv, f_r, f_i, out_k, out_v);
    // 3) attention (tf32 mma + ldmatrix, causal block skip)
    flash_attn<<<dim3(SS / 128, HH, BB), 256, FA_BYTES>>>(qkv, out_k, out_v,
                                                          mask, attn);
    // 4) output projection (tf32 mma.sync + ldmatrix)
    gemm_mma<<<dim3(NSTATE / 128, M / 128), 256>>>(attn, W_o, nullptr, out,
                                                   M, NSTATE, NSTATE);
}